// round 15
// baseline (speedup 1.0000x reference)
#include <cuda_runtime.h>
#include <cstdint>

#define HID   128
#define NEDGE 800000
#define NNODE 50000
#define NTILE 6250          // NEDGE / 128
#define NTILEN 391          // ceil(NNODE / 128)
#define GRID_E 444          // 3 CTAs/SM * 148 SMs
#define EBS 80              // bf16x2 words per edge row (LDS.128 conflict-free)
#define DS  132             // sD stride in floats
#define HBS 140             // tf32 words per node row in node_mma

// ---- scratch (static __device__ arrays; allocation-free) ----
__device__ unsigned short g_Ha16[NNODE * HID];   // h @ Wa, bf16
__device__ unsigned short g_Hb16[NNODE * HID];   // h @ Wb, bf16
__device__ float g_a[NEDGE];
__device__ int   g_row[NEDGE];
__device__ int   g_col[NEDGE];
__device__ int   g_deg[NNODE];
__device__ int   g_off[NNODE + 1];
__device__ int   g_pos[NNODE];
__device__ int   g_eidx[NEDGE];
__device__ float g_ps[512];
__device__ float g_stats[2];
__device__ uint4 g_Af[64 * 32];          // bf16 A frags for edge_mma
__device__ uint4 g_Wab[2 * 8 * 16 * 32]; // tf32 A frags for node_mma

// ---- helpers ----
__device__ __forceinline__ uint32_t pk_bf(float lo, float hi) {
    uint32_t r;   // cvt.bf16x2: first src -> upper half
    asm("cvt.rn.bf16x2.f32 %0, %1, %2;" : "=r"(r) : "f"(hi), "f"(lo));
    return r;
}
__device__ __forceinline__ unsigned short f2bf(float x) {
    return (unsigned short)(pk_bf(x, x) & 0xffffu);
}
__device__ __forceinline__ uint32_t f2tf32(float x) {
    uint32_t u;
    asm("cvt.rna.tf32.f32 %0, %1;" : "=r"(u) : "f"(x));
    return u;
}
__device__ __forceinline__ void mma_bf(float* c, const uint4& a, uint32_t b0, uint32_t b1) {
    asm volatile(
        "mma.sync.aligned.m16n8k16.row.col.f32.bf16.bf16.f32 "
        "{%0,%1,%2,%3}, {%4,%5,%6,%7}, {%8,%9}, {%0,%1,%2,%3};"
        : "+f"(c[0]), "+f"(c[1]), "+f"(c[2]), "+f"(c[3])
        : "r"(a.x), "r"(a.y), "r"(a.z), "r"(a.w), "r"(b0), "r"(b1));
}
__device__ __forceinline__ void mma_tf(float* c, const uint4& a, uint32_t b0, uint32_t b1) {
    asm volatile(
        "mma.sync.aligned.m16n8k8.row.col.f32.tf32.tf32.f32 "
        "{%0,%1,%2,%3}, {%4,%5,%6,%7}, {%8,%9}, {%0,%1,%2,%3};"
        : "+f"(c[0]), "+f"(c[1]), "+f"(c[2]), "+f"(c[3])
        : "r"(a.x), "r"(a.y), "r"(a.z), "r"(a.w), "r"(b0), "r"(b1));
}
__device__ __forceinline__ float elu(float x) {
    return x > 0.f ? x : (__expf(x) - 1.f);
}

// ============================================================
// Kernel 1: convert (fused dtype-detect + clamp + row histogram)
// ============================================================
__global__ void __launch_bounds__(256) convert(const void* __restrict__ eiraw) {
    __shared__ int s_is64;
    if (threadIdx.x == 0) {
        const int* p = (const int*)eiraw;
        int orv = 0;
#pragma unroll
        for (int i = 0; i < 64; i++) orv |= p[2 * i + 1];
        s_is64 = (orv == 0);
    }
    __syncthreads();
    int e = blockIdx.x * 256 + threadIdx.x;
    if (e >= NEDGE) return;
    int row, col;
    if (s_is64) {
        const long long* p = (const long long*)eiraw;
        row = (int)p[e]; col = (int)p[NEDGE + e];
    } else {
        const int* p = (const int*)eiraw;
        row = p[e]; col = p[NEDGE + e];
    }
    row = min(max(row, 0), NNODE - 1);
    col = min(max(col, 0), NNODE - 1);
    g_row[e] = row;
    g_col[e] = col;
    atomicAdd(&g_deg[row], 1);
}

// ============================================================
// Kernel 2: prep — fused A-fragment packing (blocks 0-7: Wc bf16;
//   blocks 8-39: Wa|Wb tf32)
// ============================================================
__global__ void __launch_bounds__(256) prep(const float* __restrict__ W1) {
    if (blockIdx.x < 8) {
        int t = blockIdx.x * 256 + threadIdx.x;   // 0..2047
        int lane = t & 31, K16 = (t >> 5) & 7, wid = t >> 8;
        int tg = lane >> 2, tk = lane & 3;
        int o0 = 16 * wid + tg;
        int kb = K16 * 16 + 2 * tk;
        const float* Wc = W1 + 2 * HID * HID;
        uint4 r;
        r.x = pk_bf(Wc[kb * HID + o0],           Wc[(kb + 1) * HID + o0]);
        r.y = pk_bf(Wc[kb * HID + o0 + 8],       Wc[(kb + 1) * HID + o0 + 8]);
        r.z = pk_bf(Wc[(kb + 8) * HID + o0],     Wc[(kb + 9) * HID + o0]);
        r.w = pk_bf(Wc[(kb + 8) * HID + o0 + 8], Wc[(kb + 9) * HID + o0 + 8]);
        g_Af[t] = r;
    } else {
        int t = (blockIdx.x - 8) * 256 + threadIdx.x;   // 0..8191
        int lane = t & 31, K8 = (t >> 5) & 15, wid = (t >> 9) & 7, s = t >> 12;
        int tg = lane >> 2, tk = lane & 3;
        int o0 = 16 * wid + tg;
        int kb = K8 * 8;
        const float* Wb_ = W1 + (size_t)s * HID * HID;
        uint4 r;
        r.x = f2tf32(Wb_[(kb + tk) * HID + o0]);
        r.y = f2tf32(Wb_[(kb + tk) * HID + o0 + 8]);
        r.z = f2tf32(Wb_[(kb + tk + 4) * HID + o0]);
        r.w = f2tf32(Wb_[(kb + tk + 4) * HID + o0 + 8]);
        g_Wab[t] = r;
    }
}

// ============================================================
// Kernel 3: node GEMM via mma.sync tf32  ->  Ha | Hb (bf16 out)
// ============================================================
__global__ void __launch_bounds__(256, 2) node_mma(const float* __restrict__ h) {
    extern __shared__ uint32_t eb[];           // [128][HBS]
    int tid = threadIdx.x, wid = tid >> 5, lane = tid & 31;
    int tg = lane >> 2, tk = lane & 3;
    int o0 = 16 * wid + tg, o1 = o0 + 8;
    int nbase = blockIdx.x * 128;

    const float4* src = (const float4*)(h + (size_t)nbase * HID);
#pragma unroll
    for (int pass = 0; pass < 8; pass++) {
        int flat8 = pass * 256 + tid;
        int r = flat8 >> 4, kb = flat8 & 15;
        float4 v0 = make_float4(0.f, 0.f, 0.f, 0.f), v1 = v0;
        if (nbase + r < NNODE) {
            v0 = src[flat8 * 2];
            v1 = src[flat8 * 2 + 1];
        }
        uint4 q0, q1;
        q0.x = f2tf32(v0.x); q0.y = f2tf32(v1.x);
        q0.z = f2tf32(v0.y); q0.w = f2tf32(v1.y);
        q1.x = f2tf32(v0.z); q1.y = f2tf32(v1.z);
        q1.z = f2tf32(v0.w); q1.w = f2tf32(v1.w);
        uint32_t* drow = eb + r * HBS + kb * 8;
        *(uint4*)(drow)     = q0;
        *(uint4*)(drow + 4) = q1;
    }
    __syncthreads();

#pragma unroll
    for (int slab = 0; slab < 2; slab++) {
        float c0[8][4], c1[8][4];
#pragma unroll
        for (int g = 0; g < 8; g++) {
            c0[g][0]=0.f; c0[g][1]=0.f; c0[g][2]=0.f; c0[g][3]=0.f;
            c1[g][0]=0.f; c1[g][1]=0.f; c1[g][2]=0.f; c1[g][3]=0.f;
        }
        const uint32_t* ebp = eb + slab * 64 * HBS;
#pragma unroll
        for (int K8 = 0; K8 < 16; K8++) {
            uint4 a0 = g_Wab[(wid * 16 + K8) * 32 + lane];
            uint4 a1 = g_Wab[4096 + (wid * 16 + K8) * 32 + lane];
#pragma unroll
            for (int g = 0; g < 8; g++) {
                uint2 b = *(const uint2*)(ebp + (g * 8 + tg) * HBS + K8 * 8 + 2 * tk);
                mma_tf(c0[g], a0, b.x, b.y);
                mma_tf(c1[g], a1, b.x, b.y);
            }
        }
#pragma unroll
        for (int g = 0; g < 8; g++) {
            int node = nbase + slab * 64 + g * 8 + 2 * tk;
            if (node < NNODE) {
                g_Ha16[(size_t)node * HID + o0] = f2bf(c0[g][0]);
                g_Ha16[(size_t)node * HID + o1] = f2bf(c0[g][2]);
                g_Hb16[(size_t)node * HID + o0] = f2bf(c1[g][0]);
                g_Hb16[(size_t)node * HID + o1] = f2bf(c1[g][2]);
            }
            if (node + 1 < NNODE) {
                g_Ha16[(size_t)(node + 1) * HID + o0] = f2bf(c0[g][1]);
                g_Ha16[(size_t)(node + 1) * HID + o1] = f2bf(c0[g][3]);
                g_Hb16[(size_t)(node + 1) * HID + o0] = f2bf(c1[g][1]);
                g_Hb16[(size_t)(node + 1) * HID + o1] = f2bf(c1[g][3]);
            }
        }
    }
}

// ============================================================
// Kernel 4: edge GEMM (unchanged from R14 pass)
// ============================================================
__global__ void __launch_bounds__(256, 3) edge_mma(const float* __restrict__ ea,
                                                   const float* __restrict__ b1,
                                                   const float* __restrict__ W2,
                                                   const float* __restrict__ b2) {
    extern __shared__ char sm[];
    uint32_t*       eb   = (uint32_t*)sm;            // [128][80]
    float*          sD   = (float*)(sm + 40960);     // [64][132]
    unsigned short* idxs = (unsigned short*)(sm + 74752);  // [256]
    float*          b1s  = (float*)(sm + 75264);
    float*          w2s  = (float*)(sm + 75776);

    int tid = threadIdx.x, wid = tid >> 5, lane = tid & 31;
    int tg = lane >> 2, tk = lane & 3;
    int o0 = 16 * wid + tg, o1 = o0 + 8;
    float b2v = b2[0];
    float ls = 0.f;

    if (tid < 128) { b1s[tid] = b1[tid]; w2s[tid] = W2[tid]; }

    for (int tile = blockIdx.x; tile < NTILE; tile += GRID_E) {
        int e_ = tid & 127;
        idxs[tid] = (unsigned short)((tid < 128) ? g_row[tile * 128 + e_]
                                                 : g_col[tile * 128 + e_]);
        const float4* src = (const float4*)(ea + (size_t)tile * 128 * HID);
#pragma unroll
        for (int pass = 0; pass < 8; pass++) {
            int flat8 = pass * 256 + tid;
            int r = flat8 >> 4, kb = flat8 & 15;
            float4 v0 = src[flat8 * 2];
            float4 v1 = src[flat8 * 2 + 1];
            uint32_t* dr = eb + r * EBS + (kb >> 2) * 16 + (kb & 3);
            dr[0]  = pk_bf(v0.x, v0.y);
            dr[4]  = pk_bf(v0.z, v0.w);
            dr[8]  = pk_bf(v1.x, v1.y);
            dr[12] = pk_bf(v1.z, v1.w);
        }
        __syncthreads();

#pragma unroll
        for (int slab = 0; slab < 2; slab++) {
            float c[8][4];
#pragma unroll
            for (int g = 0; g < 8; g++) { c[g][0]=0.f; c[g][1]=0.f; c[g][2]=0.f; c[g][3]=0.f; }
            const uint32_t* ebp = eb + slab * 64 * EBS;
#pragma unroll
            for (int K32 = 0; K32 < 4; K32++) {
                uint4 af0 = g_Af[(wid * 8 + 2 * K32) * 32 + lane];
                uint4 af1 = g_Af[(wid * 8 + 2 * K32 + 1) * 32 + lane];
#pragma unroll
                for (int g = 0; g < 8; g++) {
                    uint4 b = *(const uint4*)(ebp + (g * 8 + tg) * EBS + K32 * 16 + 4 * tk);
                    mma_bf(c[g], af0, b.x, b.y);
                    mma_bf(c[g], af1, b.z, b.w);
                }
            }
#pragma unroll
            for (int g = 0; g < 8; g++) {
                int el = g * 8 + 2 * tk;
                sD[el * DS + o0]       = c[g][0];
                sD[(el + 1) * DS + o0] = c[g][1];
                sD[el * DS + o1]       = c[g][2];
                sD[(el + 1) * DS + o1] = c[g][3];
            }
            __syncthreads();

#pragma unroll
            for (int i = 0; i < 8; i++) {
                int el = wid * 8 + i;
                int e = slab * 64 + el;
                int row = idxs[e], col = idxs[128 + e];
                float4 d   = *(float4*)&sD[el * DS + 4 * lane];
                uint2 haw  = *(const uint2*)(g_Ha16 + (size_t)row * HID + 4 * lane);
                uint2 hbw  = *(const uint2*)(g_Hb16 + (size_t)col * HID + 4 * lane);
                float4 b1v = *(const float4*)&b1s[4 * lane];
                float4 w2v = *(const float4*)&w2s[4 * lane];
                float ha0 = __uint_as_float(haw.x << 16);
                float ha1 = __uint_as_float(haw.x & 0xffff0000u);
                float ha2 = __uint_as_float(haw.y << 16);
                float ha3 = __uint_as_float(haw.y & 0xffff0000u);
                float hb0 = __uint_as_float(hbw.x << 16);
                float hb1 = __uint_as_float(hbw.x & 0xffff0000u);
                float hb2 = __uint_as_float(hbw.y << 16);
                float hb3 = __uint_as_float(hbw.y & 0xffff0000u);
                float partial =
                    elu(d.x + ha0 + hb0 + b1v.x) * w2v.x +
                    elu(d.y + ha1 + hb1 + b1v.y) * w2v.y +
                    elu(d.z + ha2 + hb2 + b1v.z) * w2v.z +
                    elu(d.w + ha3 + hb3 + b1v.w) * w2v.w;
#pragma unroll
                for (int off = 16; off; off >>= 1)
                    partial += __shfl_xor_sync(0xffffffffu, partial, off);
                float a = partial + b2v;
                float lg = a > 0.f ? a : 0.2f * a;
                if (lane == 0) g_a[tile * 128 + e] = lg;
                ls += __expf(lg);
            }
            __syncthreads();
        }
    }

    float* red = (float*)idxs;
    if (lane == 0) red[wid] = ls;
    __syncthreads();
    if (tid == 0) {
        float S = 0.f;
#pragma unroll
        for (int w = 0; w < 8; w++) S += red[w];
        g_ps[blockIdx.x] = S;
    }
}

// ============================================================
// Kernel 5: blocked prefix scan of g_deg -> g_off / g_pos
// ============================================================
__global__ void __launch_bounds__(1024) prefix() {
    __shared__ int bs[1024];
    const int CH = (NNODE + 1023) / 1024;   // 49
    int t = threadIdx.x;
    int base = t * CH;
    int s = 0;
    for (int i = 0; i < CH; i++) {
        int idx = base + i;
        if (idx < NNODE) s += g_deg[idx];
    }
    bs[t] = s;
    __syncthreads();
    for (int off = 1; off < 1024; off <<= 1) {
        int v = (t >= off) ? bs[t - off] : 0;
        __syncthreads();
        bs[t] += v;
        __syncthreads();
    }
    int run = t ? bs[t - 1] : 0;
    for (int i = 0; i < CH; i++) {
        int idx = base + i;
        if (idx < NNODE) {
            g_off[idx] = run;
            g_pos[idx] = run;
            run += g_deg[idx];
        }
    }
    if (t == 1023) g_off[NNODE] = bs[1023];
}

// ============================================================
// Kernel 6: fill CSR edge lists
// ============================================================
__global__ void __launch_bounds__(256) fill_csr() {
    int e = blockIdx.x * 256 + threadIdx.x;
    if (e >= NEDGE) return;
    int pos = atomicAdd(&g_pos[g_row[e]], 1);
    g_eidx[pos] = e;
}

// ============================================================
// Kernel 7: final softmax reduction over GRID_E partials
// ============================================================
__global__ void softmax_final() {
    int t = threadIdx.x;
    __shared__ float ss_[512];
    ss_[t] = (t < GRID_E) ? g_ps[t] : 0.f;
    __syncthreads();
    for (int off = 256; off; off >>= 1) {
        if (t < off) ss_[t] += ss_[t + off];
        __syncthreads();
    }
    if (t == 0) g_stats[1] = 1.f / ss_[0];
}

// ============================================================
// Kernel 8: gather aggregation (warp per node, no atomics)
//   out[n] = sum_{e in CSR[n]} alpha_e * h[col_e]
// ============================================================
__global__ void __launch_bounds__(256) gather(const float* __restrict__ h,
                                              float* __restrict__ out) {
    int node = blockIdx.x * 8 + (threadIdx.x >> 5);
    int lane = threadIdx.x & 31;
    if (node >= NNODE) return;
    int start = g_off[node], end = g_off[node + 1];
    float inv = g_stats[1];
    float4 acc = make_float4(0.f, 0.f, 0.f, 0.f);
    for (int i = start; i < end; i += 32) {
        int n = min(32, end - i);
        int cl = 0; float al = 0.f;
        if (lane < n) {
            int eid = g_eidx[i + lane];
            cl = g_col[eid];
            al = __expf(g_a[eid]) * inv;
        }
        for (int j = 0; j < n; j++) {
            int col = __shfl_sync(0xffffffffu, cl, j);
            float alpha = __shfl_sync(0xffffffffu, al, j);
            float4 hv = *(const float4*)&h[(size_t)col * HID + 4 * lane];
            acc.x += alpha * hv.x;
            acc.y += alpha * hv.y;
            acc.z += alpha * hv.z;
            acc.w += alpha * hv.w;
        }
    }
    *(float4*)&out[(size_t)node * HID + 4 * lane] = acc;
}

// ============================================================
extern "C" void kernel_launch(void* const* d_in, const int* in_sizes, int n_in,
                              void* d_out, int out_size) {
    const float* h  = (const float*)d_in[0];
    const void*  ei = (const void*)d_in[1];
    const float* ea = (const float*)d_in[2];
    const float* W1 = (const float*)d_in[3];
    const float* b1 = (const float*)d_in[4];
    const float* W2 = (const float*)d_in[5];
    const float* b2 = (const float*)d_in[6];
    float* out = (float*)d_out;

    static void* deg_ptr = nullptr;
    if (deg_ptr == nullptr) cudaGetSymbolAddress(&deg_ptr, g_deg);

    cudaFuncSetAttribute(node_mma, cudaFuncAttributeMaxDynamicSharedMemorySize, 71680);
    cudaFuncSetAttribute(edge_mma, cudaFuncAttributeMaxDynamicSharedMemorySize, 76288);

    cudaMemsetAsync(deg_ptr, 0, NNODE * sizeof(int));
    convert<<<(NEDGE + 255) / 256, 256>>>(ei);
    prep<<<40, 256>>>(W1);
    node_mma<<<NTILEN, 256, 71680>>>(h);
    edge_mma<<<GRID_E, 256, 76288>>>(ea, b1, W2, b2);
    prefix<<<1, 1024>>>();
    fill_csr<<<(NEDGE + 255) / 256, 256>>>();
    softmax_final<<<1, 512>>>();
    gather<<<(NNODE + 7) / 8, 256>>>(h, out);
}

// round 16
// speedup vs baseline: 1.1431x; 1.1431x over previous
#include <cuda_runtime.h>
#include <cstdint>

#define HID   128
#define NEDGE 800000
#define NNODE 50000
#define NTILE 6250          // NEDGE / 128
#define NTILEN 391          // ceil(NNODE / 128)
#define GRID_E 444          // 3 CTAs/SM * 148 SMs
#define EBS 80              // bf16x2 words per edge row (LDS.128 conflict-free)
#define DS  132             // sD stride in floats
#define HBS 140             // tf32 words per node row in node_mma

// ---- scratch (static __device__ arrays; allocation-free) ----
__device__ unsigned short g_Ha16[NNODE * HID];   // h @ Wa, bf16
__device__ unsigned short g_Hb16[NNODE * HID];   // h @ Wb, bf16
__device__ float g_a[NEDGE];
__device__ int   g_row[NEDGE];
__device__ int   g_col[NEDGE];
__device__ float g_ps[512];
__device__ float g_stats[2];
__device__ uint4 g_Af[64 * 32];          // bf16 A frags for edge_mma
__device__ uint4 g_Wab[2 * 8 * 16 * 32]; // tf32 A frags for node_mma

// ---- helpers ----
__device__ __forceinline__ uint32_t pk_bf(float lo, float hi) {
    uint32_t r;   // cvt.bf16x2: first src -> upper half
    asm("cvt.rn.bf16x2.f32 %0, %1, %2;" : "=r"(r) : "f"(hi), "f"(lo));
    return r;
}
__device__ __forceinline__ unsigned short f2bf(float x) {
    return (unsigned short)(pk_bf(x, x) & 0xffffu);
}
__device__ __forceinline__ uint32_t f2tf32(float x) {
    uint32_t u;
    asm("cvt.rna.tf32.f32 %0, %1;" : "=r"(u) : "f"(x));
    return u;
}
__device__ __forceinline__ void mma_bf(float* c, const uint4& a, uint32_t b0, uint32_t b1) {
    asm volatile(
        "mma.sync.aligned.m16n8k16.row.col.f32.bf16.bf16.f32 "
        "{%0,%1,%2,%3}, {%4,%5,%6,%7}, {%8,%9}, {%0,%1,%2,%3};"
        : "+f"(c[0]), "+f"(c[1]), "+f"(c[2]), "+f"(c[3])
        : "r"(a.x), "r"(a.y), "r"(a.z), "r"(a.w), "r"(b0), "r"(b1));
}
__device__ __forceinline__ void mma_tf(float* c, const uint4& a, uint32_t b0, uint32_t b1) {
    asm volatile(
        "mma.sync.aligned.m16n8k8.row.col.f32.tf32.tf32.f32 "
        "{%0,%1,%2,%3}, {%4,%5,%6,%7}, {%8,%9}, {%0,%1,%2,%3};"
        : "+f"(c[0]), "+f"(c[1]), "+f"(c[2]), "+f"(c[3])
        : "r"(a.x), "r"(a.y), "r"(a.z), "r"(a.w), "r"(b0), "r"(b1));
}
__device__ __forceinline__ float elu(float x) {
    return x > 0.f ? x : (__expf(x) - 1.f);
}

// ============================================================
// Kernel 1: convert (fused dtype-detect + clamp)
// ============================================================
__global__ void __launch_bounds__(256) convert(const void* __restrict__ eiraw) {
    __shared__ int s_is64;
    if (threadIdx.x == 0) {
        const int* p = (const int*)eiraw;
        int orv = 0;
#pragma unroll
        for (int i = 0; i < 64; i++) orv |= p[2 * i + 1];
        s_is64 = (orv == 0);
    }
    __syncthreads();
    int e = blockIdx.x * 256 + threadIdx.x;
    if (e >= NEDGE) return;
    int row, col;
    if (s_is64) {
        const long long* p = (const long long*)eiraw;
        row = (int)p[e]; col = (int)p[NEDGE + e];
    } else {
        const int* p = (const int*)eiraw;
        row = p[e]; col = p[NEDGE + e];
    }
    g_row[e] = min(max(row, 0), NNODE - 1);
    g_col[e] = min(max(col, 0), NNODE - 1);
}

// ============================================================
// Kernel 2: prep — fused A-fragment packing
// ============================================================
__global__ void __launch_bounds__(256) prep(const float* __restrict__ W1) {
    if (blockIdx.x < 8) {
        int t = blockIdx.x * 256 + threadIdx.x;   // 0..2047
        int lane = t & 31, K16 = (t >> 5) & 7, wid = t >> 8;
        int tg = lane >> 2, tk = lane & 3;
        int o0 = 16 * wid + tg;
        int kb = K16 * 16 + 2 * tk;
        const float* Wc = W1 + 2 * HID * HID;
        uint4 r;
        r.x = pk_bf(Wc[kb * HID + o0],           Wc[(kb + 1) * HID + o0]);
        r.y = pk_bf(Wc[kb * HID + o0 + 8],       Wc[(kb + 1) * HID + o0 + 8]);
        r.z = pk_bf(Wc[(kb + 8) * HID + o0],     Wc[(kb + 9) * HID + o0]);
        r.w = pk_bf(Wc[(kb + 8) * HID + o0 + 8], Wc[(kb + 9) * HID + o0 + 8]);
        g_Af[t] = r;
    } else {
        int t = (blockIdx.x - 8) * 256 + threadIdx.x;   // 0..8191
        int lane = t & 31, K8 = (t >> 5) & 15, wid = (t >> 9) & 7, s = t >> 12;
        int tg = lane >> 2, tk = lane & 3;
        int o0 = 16 * wid + tg;
        int kb = K8 * 8;
        const float* Wb_ = W1 + (size_t)s * HID * HID;
        uint4 r;
        r.x = f2tf32(Wb_[(kb + tk) * HID + o0]);
        r.y = f2tf32(Wb_[(kb + tk) * HID + o0 + 8]);
        r.z = f2tf32(Wb_[(kb + tk + 4) * HID + o0]);
        r.w = f2tf32(Wb_[(kb + tk + 4) * HID + o0 + 8]);
        g_Wab[t] = r;
    }
}

// ============================================================
// Kernel 3: node GEMM via mma.sync tf32  ->  Ha | Hb (bf16 out)
// ============================================================
__global__ void __launch_bounds__(256, 2) node_mma(const float* __restrict__ h) {
    extern __shared__ uint32_t eb[];           // [128][HBS]
    int tid = threadIdx.x, wid = tid >> 5, lane = tid & 31;
    int tg = lane >> 2, tk = lane & 3;
    int o0 = 16 * wid + tg, o1 = o0 + 8;
    int nbase = blockIdx.x * 128;

    const float4* src = (const float4*)(h + (size_t)nbase * HID);
#pragma unroll
    for (int pass = 0; pass < 8; pass++) {
        int flat8 = pass * 256 + tid;
        int r = flat8 >> 4, kb = flat8 & 15;
        float4 v0 = make_float4(0.f, 0.f, 0.f, 0.f), v1 = v0;
        if (nbase + r < NNODE) {
            v0 = src[flat8 * 2];
            v1 = src[flat8 * 2 + 1];
        }
        uint4 q0, q1;
        q0.x = f2tf32(v0.x); q0.y = f2tf32(v1.x);
        q0.z = f2tf32(v0.y); q0.w = f2tf32(v1.y);
        q1.x = f2tf32(v0.z); q1.y = f2tf32(v1.z);
        q1.z = f2tf32(v0.w); q1.w = f2tf32(v1.w);
        uint32_t* drow = eb + r * HBS + kb * 8;
        *(uint4*)(drow)     = q0;
        *(uint4*)(drow + 4) = q1;
    }
    __syncthreads();

#pragma unroll
    for (int slab = 0; slab < 2; slab++) {
        float c0[8][4], c1[8][4];
#pragma unroll
        for (int g = 0; g < 8; g++) {
            c0[g][0]=0.f; c0[g][1]=0.f; c0[g][2]=0.f; c0[g][3]=0.f;
            c1[g][0]=0.f; c1[g][1]=0.f; c1[g][2]=0.f; c1[g][3]=0.f;
        }
        const uint32_t* ebp = eb + slab * 64 * HBS;
#pragma unroll
        for (int K8 = 0; K8 < 16; K8++) {
            uint4 a0 = g_Wab[(wid * 16 + K8) * 32 + lane];
            uint4 a1 = g_Wab[4096 + (wid * 16 + K8) * 32 + lane];
#pragma unroll
            for (int g = 0; g < 8; g++) {
                uint2 b = *(const uint2*)(ebp + (g * 8 + tg) * HBS + K8 * 8 + 2 * tk);
                mma_tf(c0[g], a0, b.x, b.y);
                mma_tf(c1[g], a1, b.x, b.y);
            }
        }
#pragma unroll
        for (int g = 0; g < 8; g++) {
            int node = nbase + slab * 64 + g * 8 + 2 * tk;
            if (node < NNODE) {
                g_Ha16[(size_t)node * HID + o0] = f2bf(c0[g][0]);
                g_Ha16[(size_t)node * HID + o1] = f2bf(c0[g][2]);
                g_Hb16[(size_t)node * HID + o0] = f2bf(c1[g][0]);
                g_Hb16[(size_t)node * HID + o1] = f2bf(c1[g][2]);
            }
            if (node + 1 < NNODE) {
                g_Ha16[(size_t)(node + 1) * HID + o0] = f2bf(c0[g][1]);
                g_Ha16[(size_t)(node + 1) * HID + o1] = f2bf(c0[g][3]);
                g_Hb16[(size_t)(node + 1) * HID + o0] = f2bf(c1[g][1]);
                g_Hb16[(size_t)(node + 1) * HID + o1] = f2bf(c1[g][3]);
            }
        }
    }
}

// ============================================================
// Kernel 4: edge GEMM (bf16 mma) + coalesced epilogue + exp-sum
//   b1/W2 hoisted into registers (loop-invariant LDS removed).
// ============================================================
__global__ void __launch_bounds__(256, 3) edge_mma(const float* __restrict__ ea,
                                                   const float* __restrict__ b1,
                                                   const float* __restrict__ W2,
                                                   const float* __restrict__ b2) {
    extern __shared__ char sm[];
    uint32_t*       eb   = (uint32_t*)sm;            // [128][80]
    float*          sD   = (float*)(sm + 40960);     // [64][132]
    unsigned short* idxs = (unsigned short*)(sm + 74752);  // [256]

    int tid = threadIdx.x, wid = tid >> 5, lane = tid & 31;
    int tg = lane >> 2, tk = lane & 3;
    int o0 = 16 * wid + tg, o1 = o0 + 8;
    float b2v = b2[0];
    float ls = 0.f;

    // loop-invariant epilogue operands in registers (was: per-edge LDS)
    float4 b1v = *(const float4*)&b1[4 * lane];
    float4 w2v = *(const float4*)&W2[4 * lane];

    for (int tile = blockIdx.x; tile < NTILE; tile += GRID_E) {
        int e_ = tid & 127;
        idxs[tid] = (unsigned short)((tid < 128) ? g_row[tile * 128 + e_]
                                                 : g_col[tile * 128 + e_]);
        const float4* src = (const float4*)(ea + (size_t)tile * 128 * HID);
#pragma unroll
        for (int pass = 0; pass < 8; pass++) {
            int flat8 = pass * 256 + tid;          // 8-float chunk (0..2047)
            int r = flat8 >> 4, kb = flat8 & 15;
            float4 v0 = src[flat8 * 2];
            float4 v1 = src[flat8 * 2 + 1];
            uint32_t* dr = eb + r * EBS + (kb >> 2) * 16 + (kb & 3);
            dr[0]  = pk_bf(v0.x, v0.y);
            dr[4]  = pk_bf(v0.z, v0.w);
            dr[8]  = pk_bf(v1.x, v1.y);
            dr[12] = pk_bf(v1.z, v1.w);
        }
        __syncthreads();

#pragma unroll
        for (int slab = 0; slab < 2; slab++) {
            float c[8][4];
#pragma unroll
            for (int g = 0; g < 8; g++) { c[g][0]=0.f; c[g][1]=0.f; c[g][2]=0.f; c[g][3]=0.f; }
            const uint32_t* ebp = eb + slab * 64 * EBS;
#pragma unroll
            for (int K32 = 0; K32 < 4; K32++) {
                uint4 af0 = g_Af[(wid * 8 + 2 * K32) * 32 + lane];
                uint4 af1 = g_Af[(wid * 8 + 2 * K32 + 1) * 32 + lane];
#pragma unroll
                for (int g = 0; g < 8; g++) {
                    uint4 b = *(const uint4*)(ebp + (g * 8 + tg) * EBS + K32 * 16 + 4 * tk);
                    mma_bf(c[g], af0, b.x, b.y);
                    mma_bf(c[g], af1, b.z, b.w);
                }
            }
#pragma unroll
            for (int g = 0; g < 8; g++) {
                int el = g * 8 + 2 * tk;
                sD[el * DS + o0]       = c[g][0];
                sD[(el + 1) * DS + o0] = c[g][1];
                sD[el * DS + o1]       = c[g][2];
                sD[(el + 1) * DS + o1] = c[g][3];
            }
            __syncthreads();

#pragma unroll
            for (int i = 0; i < 8; i++) {
                int el = wid * 8 + i;
                int e = slab * 64 + el;
                int row = idxs[e], col = idxs[128 + e];
                float4 d   = *(float4*)&sD[el * DS + 4 * lane];
                uint2 haw  = *(const uint2*)(g_Ha16 + (size_t)row * HID + 4 * lane);
                uint2 hbw  = *(const uint2*)(g_Hb16 + (size_t)col * HID + 4 * lane);
                float ha0 = __uint_as_float(haw.x << 16);
                float ha1 = __uint_as_float(haw.x & 0xffff0000u);
                float ha2 = __uint_as_float(haw.y << 16);
                float ha3 = __uint_as_float(haw.y & 0xffff0000u);
                float hb0 = __uint_as_float(hbw.x << 16);
                float hb1 = __uint_as_float(hbw.x & 0xffff0000u);
                float hb2 = __uint_as_float(hbw.y << 16);
                float hb3 = __uint_as_float(hbw.y & 0xffff0000u);
                float partial =
                    elu(d.x + ha0 + hb0 + b1v.x) * w2v.x +
                    elu(d.y + ha1 + hb1 + b1v.y) * w2v.y +
                    elu(d.z + ha2 + hb2 + b1v.z) * w2v.z +
                    elu(d.w + ha3 + hb3 + b1v.w) * w2v.w;
#pragma unroll
                for (int off = 16; off; off >>= 1)
                    partial += __shfl_xor_sync(0xffffffffu, partial, off);
                float a = partial + b2v;
                float lg = a > 0.f ? a : 0.2f * a;
                if (lane == 0) g_a[tile * 128 + e] = lg;
                ls += __expf(lg);
            }
            __syncthreads();
        }
    }

    // ---- block-reduce exp-sum partials (ls identical across lanes) ----
    float* red = (float*)idxs;
    if (lane == 0) red[wid] = ls;
    __syncthreads();
    if (tid == 0) {
        float S = 0.f;
#pragma unroll
        for (int w = 0; w < 8; w++) S += red[w];
        g_ps[blockIdx.x] = S;
    }
}

// ============================================================
// Kernel 5: final softmax reduction over GRID_E partials
// ============================================================
__global__ void softmax_final() {
    int t = threadIdx.x;
    __shared__ float ss_[512];
    ss_[t] = (t < GRID_E) ? g_ps[t] : 0.f;
    __syncthreads();
    for (int off = 256; off; off >>= 1) {
        if (t < off) ss_[t] += ss_[t + off];
        __syncthreads();
    }
    if (t == 0) { g_stats[0] = 0.f; g_stats[1] = 1.f / ss_[0]; }
}

// ============================================================
// Kernel 6: scatter  out[row] += alpha_e * h[col]   (red.v4.f32)
// ============================================================
__global__ void __launch_bounds__(256) scatter(const float* __restrict__ h,
                                               float* __restrict__ out) {
    int gw = (blockIdx.x * 256 + threadIdx.x) >> 5;
    int l = threadIdx.x & 31;
    float inv = g_stats[1];
    int e0 = gw * 4;
#pragma unroll
    for (int e = 0; e < 4; e++) {
        int ed = e0 + e;
        if (ed >= NEDGE) return;
        float alpha = __expf(g_a[ed]) * inv;
        int row = g_row[ed];
        int col = g_col[ed];
        float4 hv = *(const float4*)&h[(size_t)col * HID + 4 * l];
        float* dst = &out[(size_t)row * HID + 4 * l];
        asm volatile("red.global.add.v4.f32 [%0], {%1, %2, %3, %4};"
                     :: "l"(dst), "f"(alpha * hv.x), "f"(alpha * hv.y),
                        "f"(alpha * hv.z), "f"(alpha * hv.w)
                     : "memory");
    }
}

// ============================================================
extern "C" void kernel_launch(void* const* d_in, const int* in_sizes, int n_in,
                              void* d_out, int out_size) {
    const float* h  = (const float*)d_in[0];
    const void*  ei = (const void*)d_in[1];
    const float* ea = (const float*)d_in[2];
    const float* W1 = (const float*)d_in[3];
    const float* b1 = (const float*)d_in[4];
    const float* W2 = (const float*)d_in[5];
    const float* b2 = (const float*)d_in[6];
    float* out = (float*)d_out;

    cudaFuncSetAttribute(node_mma, cudaFuncAttributeMaxDynamicSharedMemorySize, 71680);
    cudaFuncSetAttribute(edge_mma, cudaFuncAttributeMaxDynamicSharedMemorySize, 76288);

    convert<<<(NEDGE + 255) / 256, 256>>>(ei);
    prep<<<40, 256>>>(W1);
    node_mma<<<NTILEN, 256, 71680>>>(h);
    cudaMemsetAsync(d_out, 0, (size_t)out_size * sizeof(float));
    edge_mma<<<GRID_E, 256, 76288>>>(ea, b1, W2, b2);
    softmax_final<<<1, 512>>>();
    scatter<<<25000, 256>>>(h, out);
}

// round 17
// speedup vs baseline: 1.2573x; 1.0999x over previous
#include <cuda_runtime.h>
#include <cstdint>

#define HID   128
#define NEDGE 800000
#define NNODE 50000
#define NTILE 6250          // NEDGE / 128
#define NTILEN 391          // ceil(NNODE / 128)
#define GRID_E 592          // 4 CTAs/SM * 148 SMs
#define EBS 80              // bf16x2 words per edge row (LDS.128 conflict-free)
#define DS16 136            // sD stride in bf16 halves (LDS.64 conflict-free)
#define HBS 140             // tf32 words per node row in node_mma

// ---- scratch (static __device__ arrays; allocation-free) ----
__device__ unsigned short g_Ha16[NNODE * HID];   // h @ Wa, bf16
__device__ unsigned short g_Hb16[NNODE * HID];   // h @ Wb, bf16
__device__ float g_a[NEDGE];
__device__ int   g_row[NEDGE];
__device__ int   g_col[NEDGE];
__device__ float g_ps[1024];
__device__ float g_stats[2];
__device__ uint4 g_Af[64 * 32];          // bf16 A frags for edge_mma
__device__ uint4 g_Wab[2 * 8 * 16 * 32]; // tf32 A frags for node_mma

// ---- helpers ----
__device__ __forceinline__ uint32_t pk_bf(float lo, float hi) {
    uint32_t r;   // cvt.bf16x2: first src -> upper half
    asm("cvt.rn.bf16x2.f32 %0, %1, %2;" : "=r"(r) : "f"(hi), "f"(lo));
    return r;
}
__device__ __forceinline__ unsigned short f2bf(float x) {
    return (unsigned short)(pk_bf(x, x) & 0xffffu);
}
__device__ __forceinline__ uint32_t f2tf32(float x) {
    uint32_t u;
    asm("cvt.rna.tf32.f32 %0, %1;" : "=r"(u) : "f"(x));
    return u;
}
__device__ __forceinline__ void mma_bf(float* c, const uint4& a, uint32_t b0, uint32_t b1) {
    asm volatile(
        "mma.sync.aligned.m16n8k16.row.col.f32.bf16.bf16.f32 "
        "{%0,%1,%2,%3}, {%4,%5,%6,%7}, {%8,%9}, {%0,%1,%2,%3};"
        : "+f"(c[0]), "+f"(c[1]), "+f"(c[2]), "+f"(c[3])
        : "r"(a.x), "r"(a.y), "r"(a.z), "r"(a.w), "r"(b0), "r"(b1));
}
__device__ __forceinline__ void mma_tf(float* c, const uint4& a, uint32_t b0, uint32_t b1) {
    asm volatile(
        "mma.sync.aligned.m16n8k8.row.col.f32.tf32.tf32.f32 "
        "{%0,%1,%2,%3}, {%4,%5,%6,%7}, {%8,%9}, {%0,%1,%2,%3};"
        : "+f"(c[0]), "+f"(c[1]), "+f"(c[2]), "+f"(c[3])
        : "r"(a.x), "r"(a.y), "r"(a.z), "r"(a.w), "r"(b0), "r"(b1));
}
__device__ __forceinline__ float elu(float x) {
    return x > 0.f ? x : (__expf(x) - 1.f);
}

// ============================================================
// Kernel 1: convert (fused dtype-detect + clamp)
// ============================================================
__global__ void __launch_bounds__(256) convert(const void* __restrict__ eiraw) {
    __shared__ int s_is64;
    if (threadIdx.x == 0) {
        const int* p = (const int*)eiraw;
        int orv = 0;
#pragma unroll
        for (int i = 0; i < 64; i++) orv |= p[2 * i + 1];
        s_is64 = (orv == 0);
    }
    __syncthreads();
    int e = blockIdx.x * 256 + threadIdx.x;
    if (e >= NEDGE) return;
    int row, col;
    if (s_is64) {
        const long long* p = (const long long*)eiraw;
        row = (int)p[e]; col = (int)p[NEDGE + e];
    } else {
        const int* p = (const int*)eiraw;
        row = p[e]; col = p[NEDGE + e];
    }
    g_row[e] = min(max(row, 0), NNODE - 1);
    g_col[e] = min(max(col, 0), NNODE - 1);
}

// ============================================================
// Kernel 2: prep — fused A-fragment packing
// ============================================================
__global__ void __launch_bounds__(256) prep(const float* __restrict__ W1) {
    if (blockIdx.x < 8) {
        int t = blockIdx.x * 256 + threadIdx.x;   // 0..2047
        int lane = t & 31, K16 = (t >> 5) & 7, wid = t >> 8;
        int tg = lane >> 2, tk = lane & 3;
        int o0 = 16 * wid + tg;
        int kb = K16 * 16 + 2 * tk;
        const float* Wc = W1 + 2 * HID * HID;
        uint4 r;
        r.x = pk_bf(Wc[kb * HID + o0],           Wc[(kb + 1) * HID + o0]);
        r.y = pk_bf(Wc[kb * HID + o0 + 8],       Wc[(kb + 1) * HID + o0 + 8]);
        r.z = pk_bf(Wc[(kb + 8) * HID + o0],     Wc[(kb + 9) * HID + o0]);
        r.w = pk_bf(Wc[(kb + 8) * HID + o0 + 8], Wc[(kb + 9) * HID + o0 + 8]);
        g_Af[t] = r;
    } else {
        int t = (blockIdx.x - 8) * 256 + threadIdx.x;   // 0..8191
        int lane = t & 31, K8 = (t >> 5) & 15, wid = (t >> 9) & 7, s = t >> 12;
        int tg = lane >> 2, tk = lane & 3;
        int o0 = 16 * wid + tg;
        int kb = K8 * 8;
        const float* Wb_ = W1 + (size_t)s * HID * HID;
        uint4 r;
        r.x = f2tf32(Wb_[(kb + tk) * HID + o0]);
        r.y = f2tf32(Wb_[(kb + tk) * HID + o0 + 8]);
        r.z = f2tf32(Wb_[(kb + tk + 4) * HID + o0]);
        r.w = f2tf32(Wb_[(kb + tk + 4) * HID + o0 + 8]);
        g_Wab[t] = r;
    }
}

// ============================================================
// Kernel 3: node GEMM via mma.sync tf32  ->  Ha | Hb (bf16 out)
// ============================================================
__global__ void __launch_bounds__(256, 2) node_mma(const float* __restrict__ h) {
    extern __shared__ uint32_t eb[];           // [128][HBS]
    int tid = threadIdx.x, wid = tid >> 5, lane = tid & 31;
    int tg = lane >> 2, tk = lane & 3;
    int o0 = 16 * wid + tg, o1 = o0 + 8;
    int nbase = blockIdx.x * 128;

    const float4* src = (const float4*)(h + (size_t)nbase * HID);
#pragma unroll
    for (int pass = 0; pass < 8; pass++) {
        int flat8 = pass * 256 + tid;
        int r = flat8 >> 4, kb = flat8 & 15;
        float4 v0 = make_float4(0.f, 0.f, 0.f, 0.f), v1 = v0;
        if (nbase + r < NNODE) {
            v0 = src[flat8 * 2];
            v1 = src[flat8 * 2 + 1];
        }
        uint4 q0, q1;
        q0.x = f2tf32(v0.x); q0.y = f2tf32(v1.x);
        q0.z = f2tf32(v0.y); q0.w = f2tf32(v1.y);
        q1.x = f2tf32(v0.z); q1.y = f2tf32(v1.z);
        q1.z = f2tf32(v0.w); q1.w = f2tf32(v1.w);
        uint32_t* drow = eb + r * HBS + kb * 8;
        *(uint4*)(drow)     = q0;
        *(uint4*)(drow + 4) = q1;
    }
    __syncthreads();

#pragma unroll
    for (int slab = 0; slab < 2; slab++) {
        float c0[8][4], c1[8][4];
#pragma unroll
        for (int g = 0; g < 8; g++) {
            c0[g][0]=0.f; c0[g][1]=0.f; c0[g][2]=0.f; c0[g][3]=0.f;
            c1[g][0]=0.f; c1[g][1]=0.f; c1[g][2]=0.f; c1[g][3]=0.f;
        }
        const uint32_t* ebp = eb + slab * 64 * HBS;
#pragma unroll
        for (int K8 = 0; K8 < 16; K8++) {
            uint4 a0 = g_Wab[(wid * 16 + K8) * 32 + lane];
            uint4 a1 = g_Wab[4096 + (wid * 16 + K8) * 32 + lane];
#pragma unroll
            for (int g = 0; g < 8; g++) {
                uint2 b = *(const uint2*)(ebp + (g * 8 + tg) * HBS + K8 * 8 + 2 * tk);
                mma_tf(c0[g], a0, b.x, b.y);
                mma_tf(c1[g], a1, b.x, b.y);
            }
        }
#pragma unroll
        for (int g = 0; g < 8; g++) {
            int node = nbase + slab * 64 + g * 8 + 2 * tk;
            if (node < NNODE) {
                g_Ha16[(size_t)node * HID + o0] = f2bf(c0[g][0]);
                g_Ha16[(size_t)node * HID + o1] = f2bf(c0[g][2]);
                g_Hb16[(size_t)node * HID + o0] = f2bf(c1[g][0]);
                g_Hb16[(size_t)node * HID + o1] = f2bf(c1[g][2]);
            }
            if (node + 1 < NNODE) {
                g_Ha16[(size_t)(node + 1) * HID + o0] = f2bf(c0[g][1]);
                g_Ha16[(size_t)(node + 1) * HID + o1] = f2bf(c0[g][3]);
                g_Hb16[(size_t)(node + 1) * HID + o0] = f2bf(c1[g][1]);
                g_Hb16[(size_t)(node + 1) * HID + o1] = f2bf(c1[g][3]);
            }
        }
    }
}

// ============================================================
// Kernel 4: edge GEMM (bf16 mma) + in-place bf16 D overlay
//   4 CTAs/SM: smem 41.6KB, __launch_bounds__(256,4) -> 64 regs.
//   Per slab: MMA -> sync -> C(bf16) over slab-0 region -> sync -> epilogue.
// ============================================================
__global__ void __launch_bounds__(256, 4) edge_mma(const float* __restrict__ ea,
                                                   const float* __restrict__ b1,
                                                   const float* __restrict__ W2,
                                                   const float* __restrict__ b2) {
    extern __shared__ char sm[];
    uint32_t*       eb   = (uint32_t*)sm;            // [128][80] words (40960 B)
    unsigned short* sD16 = (unsigned short*)sm;      // overlay: [64][136] halves (17408 B)
    unsigned short* idxs = (unsigned short*)(sm + 40960);  // [256]
    float*          red  = (float*)(sm + 41472);     // [16]

    int tid = threadIdx.x, wid = tid >> 5, lane = tid & 31;
    int tg = lane >> 2, tk = lane & 3;
    int o0 = 16 * wid + tg, o1 = o0 + 8;
    float b2v = b2[0];
    float ls = 0.f;

    float4 b1v = *(const float4*)&b1[4 * lane];
    float4 w2v = *(const float4*)&W2[4 * lane];

    for (int tile = blockIdx.x; tile < NTILE; tile += GRID_E) {
        int e_ = tid & 127;
        idxs[tid] = (unsigned short)((tid < 128) ? g_row[tile * 128 + e_]
                                                 : g_col[tile * 128 + e_]);
        const float4* src = (const float4*)(ea + (size_t)tile * 128 * HID);
#pragma unroll
        for (int pass = 0; pass < 8; pass++) {
            int flat8 = pass * 256 + tid;          // 8-float chunk (0..2047)
            int r = flat8 >> 4, kb = flat8 & 15;
            float4 v0 = src[flat8 * 2];
            float4 v1 = src[flat8 * 2 + 1];
            uint32_t* dr = eb + r * EBS + (kb >> 2) * 16 + (kb & 3);
            dr[0]  = pk_bf(v0.x, v0.y);
            dr[4]  = pk_bf(v0.z, v0.w);
            dr[8]  = pk_bf(v1.x, v1.y);
            dr[12] = pk_bf(v1.z, v1.w);
        }
        __syncthreads();

#pragma unroll
        for (int slab = 0; slab < 2; slab++) {
            float c[8][4];
#pragma unroll
            for (int g = 0; g < 8; g++) { c[g][0]=0.f; c[g][1]=0.f; c[g][2]=0.f; c[g][3]=0.f; }
            const uint32_t* ebp = eb + slab * 64 * EBS;
#pragma unroll
            for (int K32 = 0; K32 < 4; K32++) {
                uint4 af0 = g_Af[(wid * 8 + 2 * K32) * 32 + lane];
                uint4 af1 = g_Af[(wid * 8 + 2 * K32 + 1) * 32 + lane];
#pragma unroll
                for (int g = 0; g < 8; g++) {
                    uint4 b = *(const uint4*)(ebp + (g * 8 + tg) * EBS + K32 * 16 + 4 * tk);
                    mma_bf(c[g], af0, b.x, b.y);
                    mma_bf(c[g], af1, b.z, b.w);
                }
            }
            // all B reads of this slab complete CTA-wide (and, for slab 1,
            // the slab-0 epilogue is done) before overwriting the overlay
            __syncthreads();
#pragma unroll
            for (int g = 0; g < 8; g++) {
                int el = g * 8 + 2 * tk;
                sD16[el * DS16 + o0]       = f2bf(c[g][0]);
                sD16[el * DS16 + o1]       = f2bf(c[g][2]);
                sD16[(el + 1) * DS16 + o0] = f2bf(c[g][1]);
                sD16[(el + 1) * DS16 + o1] = f2bf(c[g][3]);
            }
            __syncthreads();

#pragma unroll
            for (int i = 0; i < 8; i++) {
                int el = wid * 8 + i;
                int e = slab * 64 + el;
                int row = idxs[e], col = idxs[128 + e];
                uint2 dw   = *(const uint2*)(sD16 + el * DS16 + 4 * lane);
                uint2 haw  = *(const uint2*)(g_Ha16 + (size_t)row * HID + 4 * lane);
                uint2 hbw  = *(const uint2*)(g_Hb16 + (size_t)col * HID + 4 * lane);
                float d0 = __uint_as_float(dw.x << 16);
                float d1 = __uint_as_float(dw.x & 0xffff0000u);
                float d2 = __uint_as_float(dw.y << 16);
                float d3 = __uint_as_float(dw.y & 0xffff0000u);
                float ha0 = __uint_as_float(haw.x << 16);
                float ha1 = __uint_as_float(haw.x & 0xffff0000u);
                float ha2 = __uint_as_float(haw.y << 16);
                float ha3 = __uint_as_float(haw.y & 0xffff0000u);
                float hb0 = __uint_as_float(hbw.x << 16);
                float hb1 = __uint_as_float(hbw.x & 0xffff0000u);
                float hb2 = __uint_as_float(hbw.y << 16);
                float hb3 = __uint_as_float(hbw.y & 0xffff0000u);
                float partial =
                    elu(d0 + ha0 + hb0 + b1v.x) * w2v.x +
                    elu(d1 + ha1 + hb1 + b1v.y) * w2v.y +
                    elu(d2 + ha2 + hb2 + b1v.z) * w2v.z +
                    elu(d3 + ha3 + hb3 + b1v.w) * w2v.w;
#pragma unroll
                for (int off = 16; off; off >>= 1)
                    partial += __shfl_xor_sync(0xffffffffu, partial, off);
                float a = partial + b2v;
                float lg = a > 0.f ? a : 0.2f * a;
                if (lane == 0) g_a[tile * 128 + e] = lg;
                ls += __expf(lg);
            }
        }
        __syncthreads();   // epilogue(slab 1) done before next tile's loads
    }

    // ---- block-reduce exp-sum partials (ls identical across lanes) ----
    if (lane == 0) red[wid] = ls;
    __syncthreads();
    if (tid == 0) {
        float S = 0.f;
#pragma unroll
        for (int w = 0; w < 8; w++) S += red[w];
        g_ps[blockIdx.x] = S;
    }
}

// ============================================================
// Kernel 5: final softmax reduction over GRID_E partials
// ============================================================
__global__ void softmax_final() {
    int t = threadIdx.x;
    __shared__ float ss_[1024];
    ss_[t] = (t < GRID_E) ? g_ps[t] : 0.f;
    __syncthreads();
    for (int off = 512; off; off >>= 1) {
        if (t < off) ss_[t] += ss_[t + off];
        __syncthreads();
    }
    if (t == 0) { g_stats[0] = 0.f; g_stats[1] = 1.f / ss_[0]; }
}

// ============================================================
// Kernel 6: scatter  out[row] += alpha_e * h[col]   (red.v4.f32)
// ============================================================
__global__ void __launch_bounds__(256) scatter(const float* __restrict__ h,
                                               float* __restrict__ out) {
    int gw = (blockIdx.x * 256 + threadIdx.x) >> 5;
    int l = threadIdx.x & 31;
    float inv = g_stats[1];
    int e0 = gw * 4;
#pragma unroll
    for (int e = 0; e < 4; e++) {
        int ed = e0 + e;
        if (ed >= NEDGE) return;
        float alpha = __expf(g_a[ed]) * inv;
        int row = g_row[ed];
        int col = g_col[ed];
        float4 hv = *(const float4*)&h[(size_t)col * HID + 4 * l];
        float* dst = &out[(size_t)row * HID + 4 * l];
        asm volatile("red.global.add.v4.f32 [%0], {%1, %2, %3, %4};"
                     :: "l"(dst), "f"(alpha * hv.x), "f"(alpha * hv.y),
                        "f"(alpha * hv.z), "f"(alpha * hv.w)
                     : "memory");
    }
}

// ============================================================
extern "C" void kernel_launch(void* const* d_in, const int* in_sizes, int n_in,
                              void* d_out, int out_size) {
    const float* h  = (const float*)d_in[0];
    const void*  ei = (const void*)d_in[1];
    const float* ea = (const float*)d_in[2];
    const float* W1 = (const float*)d_in[3];
    const float* b1 = (const float*)d_in[4];
    const float* W2 = (const float*)d_in[5];
    const float* b2 = (const float*)d_in[6];
    float* out = (float*)d_out;

    cudaFuncSetAttribute(node_mma, cudaFuncAttributeMaxDynamicSharedMemorySize, 71680);
    cudaFuncSetAttribute(edge_mma, cudaFuncAttributeMaxDynamicSharedMemorySize, 41600);

    convert<<<(NEDGE + 255) / 256, 256>>>(ei);
    prep<<<40, 256>>>(W1);
    node_mma<<<NTILEN, 256, 71680>>>(h);
    cudaMemsetAsync(d_out, 0, (size_t)out_size * sizeof(float));
    edge_mma<<<GRID_E, 256, 41600>>>(ea, b1, W2, b2);
    softmax_final<<<1, 1024>>>();
    scatter<<<25000, 256>>>(h, out);
}